// round 11
// baseline (speedup 1.0000x reference)
#include <cuda_runtime.h>
#include <cuda_bf16.h>

// B=8, C=128, IC=64, H=W=64, N=4096, M=1024 (pooled 32x32)

__device__ float g_p[8][1024];
__device__ float g_t[8][4096];
__device__ float g_xg[8][1024][64];
__device__ float g_psort[8][1024];
__device__ int   g_perm[8][1024];
__device__ unsigned g_w2bT[4096];         // w2 packed bf16x2, TRANSPOSED [cc][co]
__device__ float g_z[8][1024][128];       // (xg @ w2^T)/1024
__device__ float2 g_T12[8][1025][128];    // interleaved (T1,T2) suffix tables

// ---- helpers --------------------------------------------------------------
__device__ __forceinline__ unsigned pbf2(float lo, float hi) {
    unsigned r; asm("cvt.rn.bf16x2.f32 %0, %1, %2;" : "=r"(r) : "f"(hi), "f"(lo));
    return r;
}
__device__ __forceinline__ void mma16816(float* d, unsigned a0, unsigned a1,
                                         unsigned a2, unsigned a3,
                                         unsigned b0, unsigned b1) {
    asm("mma.sync.aligned.m16n8k16.row.col.f32.bf16.bf16.f32 "
        "{%0,%1,%2,%3}, {%4,%5,%6,%7}, {%8,%9}, {%0,%1,%2,%3};"
        : "+f"(d[0]), "+f"(d[1]), "+f"(d[2]), "+f"(d[3])
        : "r"(a0), "r"(a1), "r"(a2), "r"(a3), "r"(b0), "r"(b1));
}

// ---------------------------------------------------------------------------
// K1: fused conv1+conv4 via bf16 mma.sync, in-register maxpool,
//     + folded conv3 scalar t.  (unchanged from R9)
// ---------------------------------------------------------------------------
#define SWS 68
#define SXS 136
__global__ void __launch_bounds__(256, 2)
k1_conv(const float* __restrict__ x,
        const float* __restrict__ w1, const float* __restrict__ b1,
        const float* __restrict__ w3, const float* __restrict__ b3,
        const float* __restrict__ w4, const float* __restrict__ b4,
        const float* __restrict__ w5) {
    extern __shared__ unsigned smu[];
    unsigned* sWb  = smu;                    // 128*68
    unsigned* sXb  = smu + 128 * SWS;        // 64*136
    float* sBias = (float*)(sXb + 64 * SXS); // 128
    float* sWp   = sBias + 128;              // 64
    float* sWtp  = sWp + 64;                 // 132
    float* sPred = sWtp + 132;               // 4*32

    const int tid = threadIdx.x;
    const int pr  = blockIdx.x;
    const int b   = blockIdx.y;

    const float4* w1v = (const float4*)w1;
    const float4* w4v = (const float4*)w4;
    #pragma unroll
    for (int k = 0; k < 16; k++) {
        int v  = tid + k * 256;
        int oc = v >> 5, c4 = v & 31;
        float4 f = (oc < 64) ? w1v[oc * 32 + c4] : w4v[(oc - 64) * 32 + c4];
        *(uint2*)&sWb[oc * SWS + c4 * 2] = make_uint2(pbf2(f.x, f.y), pbf2(f.z, f.w));
    }
    const float4* xv = (const float4*)x;
    #pragma unroll
    for (int it = 0; it < 8; it++) {
        int v   = tid + it * 256;
        int cc  = v >> 5, u = v & 31;
        int r01 = u >> 4, c4 = u & 15;
        float4 fa = xv[((b * 128 + 2 * cc) * 64 + (2 * pr + r01)) * 16 + c4];
        float4 fb = xv[((b * 128 + 2 * cc + 1) * 64 + (2 * pr + r01)) * 16 + c4];
        uint4 q;
        q.x = pbf2(fa.x, fb.x); q.y = pbf2(fa.y, fb.y);
        q.z = pbf2(fa.z, fb.z); q.w = pbf2(fa.w, fb.w);
        *(uint4*)&sXb[cc * SXS + r01 * 64 + c4 * 4] = q;
    }
    if (tid < 128) {
        float acc = 0.f;
        #pragma unroll 16
        for (int i = 0; i < 64; i++) acc = fmaf(w5[i], w3[i * 128 + tid], acc);
        sWtp[tid] = acc;
        sBias[tid] = (tid < 64) ? b1[tid] : b4[tid - 64];
    } else if (tid < 160) {
        int l = tid - 128;
        float s = fmaf(w5[l], b3[l], w5[l + 32] * b3[l + 32]);
        #pragma unroll
        for (int d = 16; d >= 1; d >>= 1)
            s += __shfl_xor_sync(0xffffffffu, s, d);
        if (l == 0) sWtp[128] = s;
    }
    if (tid < 64) sWp[tid] = w5[64 + tid];
    __syncthreads();

    const int w    = tid >> 5;
    const int lane = tid & 31;
    const int g    = lane >> 2;
    const int m4   = lane & 3;
    const int ocb  = w * 16;

    float acc[16][4];
    #pragma unroll
    for (int t = 0; t < 16; t++)
        #pragma unroll
        for (int r = 0; r < 4; r++) acc[t][r] = 0.f;

    #pragma unroll
    for (int s = 0; s < 8; s++) {
        const int cc0 = s * 8;
        unsigned a0 = sWb[(ocb + g)     * SWS + cc0 + m4];
        unsigned a1 = sWb[(ocb + g + 8) * SWS + cc0 + m4];
        unsigned a2 = sWb[(ocb + g)     * SWS + cc0 + 4 + m4];
        unsigned a3 = sWb[(ocb + g + 8) * SWS + cc0 + 4 + m4];
        #pragma unroll
        for (int t = 0; t < 16; t++) {
            unsigned b0 = sXb[(cc0 + m4)     * SXS + t * 8 + g];
            unsigned b1 = sXb[(cc0 + 4 + m4) * SXS + t * 8 + g];
            mma16816(acc[t], a0, a1, a2, a3, b0, b1);
        }
    }

    if (tid < 128) {
        float a = sWtp[128];
        #pragma unroll 8
        for (int cc = 0; cc < 64; cc++) {
            unsigned u = sXb[cc * SXS + tid];
            __nv_bfloat162 h = *reinterpret_cast<__nv_bfloat162*>(&u);
            float2 f = __bfloat1622float2(h);
            a = fmaf(sWtp[2 * cc], f.x, a);
            a = fmaf(sWtp[2 * cc + 1], f.y, a);
        }
        int n = (2 * pr + (tid >> 6)) * 64 + (tid & 63);
        g_t[b][n] = a;
    }

    float pg[8], pg8[8];
    #pragma unroll
    for (int t = 0; t < 8; t++) {
        pg[t]  = fmaxf(fmaxf(acc[t][0], acc[t][1]), fmaxf(acc[t + 8][0], acc[t + 8][1]));
        pg8[t] = fmaxf(fmaxf(acc[t][2], acc[t][3]), fmaxf(acc[t + 8][2], acc[t + 8][3]));
    }

    if (w < 4) {  // xg path: oc 0..63
        int oc0 = ocb + g, oc1 = ocb + g + 8;
        float b0v = sBias[oc0], b1v = sBias[oc1];
        #pragma unroll
        for (int t = 0; t < 8; t++) {
            int mb = pr * 32 + t * 4 + m4;
            g_xg[b][mb][oc0] = pg[t]  + b0v;
            g_xg[b][mb][oc1] = pg8[t] + b1v;
        }
    } else {      // p path
        int oc0 = ocb + g, oc1 = ocb + g + 8;
        float wp0 = sWp[oc0 - 64], wp1 = sWp[oc1 - 64];
        float b0v = sBias[oc0], b1v = sBias[oc1];
        float part[8];
        #pragma unroll
        for (int t = 0; t < 8; t++)
            part[t] = fmaf(wp0, pg[t] + b0v, wp1 * (pg8[t] + b1v));
        #pragma unroll
        for (int d = 4; d < 32; d <<= 1) {
            #pragma unroll
            for (int t = 0; t < 8; t++)
                part[t] += __shfl_xor_sync(0xffffffffu, part[t], d);
        }
        if (lane < 4) {
            #pragma unroll
            for (int t = 0; t < 8; t++)
                sPred[(w - 4) * 32 + t * 4 + lane] = part[t];
        }
    }
    __syncthreads();
    if (tid < 32) {
        float pv = sPred[tid] + sPred[32 + tid] + sPred[64 + tid] + sPred[96 + tid];
        g_p[b][pr * 32 + tid] = pv;
    }
}

// ---------------------------------------------------------------------------
// K2a: bitonic sort (ping-pong smem) + w2 pack TRANSPOSED [cc][co]
// ---------------------------------------------------------------------------
__global__ void __launch_bounds__(1024) k2_sort(const float* __restrict__ w2) {
    __shared__ unsigned long long skA[1024], skB[1024];
    const int b = blockIdx.x, tid = threadIdx.x;

    {
        int u = b * 512 + tid;
        if (tid < 512) {
            float2 f = ((const float2*)w2)[u];   // u = co*32 + cc
            int co = u >> 5, cc = u & 31;
            g_w2bT[cc * 128 + co] = pbf2(f.x, f.y);
        }
    }

    float v = g_p[b][tid];
    unsigned u = __float_as_uint(v);
    u = (u & 0x80000000u) ? ~u : (u | 0x80000000u);
    unsigned long long key = ((unsigned long long)u << 32) | (unsigned)tid;

    int pb = 0;
    #pragma unroll
    for (int k = 2; k <= 1024; k <<= 1) {
        const bool up = ((tid & k) == 0);
        for (int j = k >> 1; j >= 32; j >>= 1) {
            unsigned long long* buf = pb ? skB : skA;
            buf[tid] = key;
            __syncthreads();
            unsigned long long ok = buf[tid ^ j];
            pb ^= 1;
            bool takeMin = (((tid & j) == 0) == up);
            if ((key > ok) == takeMin) key = ok;
        }
        #pragma unroll
        for (int j = ((k >> 1) < 16 ? (k >> 1) : 16); j >= 1; j >>= 1) {
            unsigned long long ok = __shfl_xor_sync(0xffffffffu, key, j);
            bool takeMin = (((tid & j) == 0) == up);
            if ((key > ok) == takeMin) key = ok;
        }
    }
    int m = (int)(key & 1023u);
    g_perm[b][tid]  = m;
    g_psort[b][tid] = g_p[b][m];
}

// ---------------------------------------------------------------------------
// K2z: z = (xg @ w2^T)/1024 via bf16 mma.  grid (32 m-tiles, 8 b), 256 thr.
// A = xg [m][cc-pairs] (stride 36), B = w2T [cc][co] (stride 132).
// Warp w: m-tile (w&1)*16, co block (w>>1)*32.
// ---------------------------------------------------------------------------
__global__ void __launch_bounds__(256)
k2z_proj() {
    __shared__ unsigned sXp[32 * 36];     // [m][cc]
    __shared__ unsigned sW2T[32 * 132];   // [cc][co]
    const int tid = threadIdx.x;
    const int mt = blockIdx.x, b = blockIdx.y;
    const int m0 = mt * 32;

    const uint4* wT4 = (const uint4*)g_w2bT;   // 1024 uint4
    #pragma unroll
    for (int k = 0; k < 4; k++) {
        int v = tid + k * 256;
        int cc = v >> 5, co4 = v & 31;
        *(uint4*)&sW2T[cc * 132 + co4 * 4] = wT4[v];
    }
    #pragma unroll
    for (int k = 0; k < 4; k++) {
        int v = tid + k * 256;
        int m = v >> 5, cc = v & 31;
        float2 f = *(const float2*)&g_xg[b][m0 + m][2 * cc];
        sXp[m * 36 + cc] = pbf2(f.x, f.y);
    }
    __syncthreads();

    const int w = tid >> 5, lane = tid & 31;
    const int g = lane >> 2, m4 = lane & 3;
    const int mb = (w & 1) * 16;
    const int cob = (w >> 1) * 32;

    float acc[4][4];
    #pragma unroll
    for (int t = 0; t < 4; t++)
        #pragma unroll
        for (int r = 0; r < 4; r++) acc[t][r] = 0.f;

    #pragma unroll
    for (int s = 0; s < 4; s++) {
        const int cc0 = s * 8;
        unsigned a0 = sXp[(mb + g)     * 36 + cc0 + m4];
        unsigned a1 = sXp[(mb + g + 8) * 36 + cc0 + m4];
        unsigned a2 = sXp[(mb + g)     * 36 + cc0 + 4 + m4];
        unsigned a3 = sXp[(mb + g + 8) * 36 + cc0 + 4 + m4];
        #pragma unroll
        for (int t = 0; t < 4; t++) {
            unsigned b0 = sW2T[(cc0 + m4)     * 132 + cob + t * 8 + g];
            unsigned b1 = sW2T[(cc0 + 4 + m4) * 132 + cob + t * 8 + g];
            mma16816(acc[t], a0, a1, a2, a3, b0, b1);
        }
    }

    const float sc = 1.0f / 1024.0f;
    const int r0 = m0 + mb + g;
    #pragma unroll
    for (int t = 0; t < 4; t++) {
        int co = cob + t * 8 + 2 * m4;
        *(float2*)&g_z[b][r0][co]     = make_float2(acc[t][0] * sc, acc[t][1] * sc);
        *(float2*)&g_z[b][r0 + 8][co] = make_float2(acc[t][2] * sc, acc[t][3] * sc);
    }
}

// ---------------------------------------------------------------------------
// K2b: suffix scan over z: 256 threads x 4 consecutive j x 4 channels.
// grid (32 channel-quads, 8 b). Writes interleaved (T1,T2).
// ---------------------------------------------------------------------------
__global__ void __launch_bounds__(256) k2_scan() {
    __shared__ float sm1[4][8], sm2[4][8];
    const int b = blockIdx.y, ig = blockIdx.x;          // channels ig*4..+3
    const int tid = threadIdx.x, lane = tid & 31, w = tid >> 5;
    const int j0 = 4 * tid;

    if (tid == 0) {
        float2* zrow = &g_T12[b][1024][ig * 4];
        *(float4*)zrow       = make_float4(0.f, 0.f, 0.f, 0.f);
        *(float4*)(zrow + 2) = make_float4(0.f, 0.f, 0.f, 0.f);
    }

    const int4   pm = ((const int4*)g_perm[b])[tid];
    const float4 ps = ((const float4*)g_psort[b])[tid];

    float4 v0 = *(const float4*)&g_z[b][pm.x][ig * 4];
    float4 v1 = *(const float4*)&g_z[b][pm.y][ig * 4];
    float4 v2 = *(const float4*)&g_z[b][pm.z][ig * 4];
    float4 v3 = *(const float4*)&g_z[b][pm.w][ig * 4];
    float vv[4][4] = {{v0.x, v0.y, v0.z, v0.w}, {v1.x, v1.y, v1.z, v1.w},
                      {v2.x, v2.y, v2.z, v2.w}, {v3.x, v3.y, v3.z, v3.w}};
    float pp[4] = {ps.x, ps.y, ps.z, ps.w};

    float s1[4], s2[4];
    #pragma unroll
    for (int c = 0; c < 4; c++) {
        s1[c] = vv[0][c] + vv[1][c] + vv[2][c] + vv[3][c];
        s2[c] = fmaf(pp[0], vv[0][c], fmaf(pp[1], vv[1][c],
                fmaf(pp[2], vv[2][c], pp[3] * vv[3][c])));
    }

    #pragma unroll
    for (int d = 1; d < 32; d <<= 1) {
        bool take = (lane + d < 32);
        #pragma unroll
        for (int c = 0; c < 4; c++) {
            float t1 = __shfl_down_sync(0xffffffffu, s1[c], d);
            float t2 = __shfl_down_sync(0xffffffffu, s2[c], d);
            if (take) { s1[c] += t1; s2[c] += t2; }
        }
    }
    if (lane == 0) {
        #pragma unroll
        for (int c = 0; c < 4; c++) { sm1[c][w] = s1[c]; sm2[c][w] = s2[c]; }
    }
    __syncthreads();
    #pragma unroll
    for (int c = 0; c < 4; c++) {
        float c1 = 0.f, c2 = 0.f;
        #pragma unroll
        for (int w2i = 0; w2i < 8; w2i++)
            if (w2i > w) { c1 += sm1[c][w2i]; c2 += sm2[c][w2i]; }
        s1[c] += c1; s2[c] += c2;
    }

    float2* base = &g_T12[b][j0][ig * 4];
    #pragma unroll
    for (int k = 0; k < 4; k++) {
        float4 oa = make_float4(s1[0], s2[0], s1[1], s2[1]);
        float4 ob = make_float4(s1[2], s2[2], s1[3], s2[3]);
        float2* dst = base + (long)k * 128;
        *(float4*)dst       = oa;
        *(float4*)(dst + 2) = ob;
        if (k < 3) {
            #pragma unroll
            for (int c = 0; c < 4; c++) {
                s1[c] -= vv[k][c];
                s2[c] = fmaf(-pp[k], vv[k][c], s2[c]);
            }
        }
    }
}

// ---------------------------------------------------------------------------
// K3: binsearch (1/px, shfl-shared), gather ONE 1KB interleaved T12 row,
//     axpy, XOR-swizzled smem transpose, BN+residual coalesced epilogue.
// grid (32, 8), 512 threads.
// ---------------------------------------------------------------------------
#define RS 140
__global__ void __launch_bounds__(512, 2)
k3_out(const float* __restrict__ x,
       const float* __restrict__ b2,
       const float* __restrict__ bg, const float* __restrict__ bb,
       const float* __restrict__ bm, const float* __restrict__ bv,
       float* __restrict__ out) {
    extern __shared__ float sm[];
    float* sPs  = sm;                 // 1024
    float* sT   = sPs + 1024;         // 128
    float* sA   = sT + 128;           // 128
    float* sB   = sA + 128;           // 128
    float* sRes = sB + 128;           // 128 co x 140 (XOR-swizzled px)

    const int tid = threadIdx.x;
    const int b   = blockIdx.y;
    const int n0  = blockIdx.x * 128;

    if (tid < 256) {
        ((float4*)sPs)[tid] = ((const float4*)g_psort[b])[tid];
    } else if (tid < 384) {
        sT[tid - 256] = g_t[b][n0 + tid - 256];
    } else {
        int c = tid - 384;
        float inv = rsqrtf(bv[c] + 1e-5f);
        float al  = bg[c] * inv;
        sA[c] = al;
        sB[c] = (b2[c] - bm[c]) * al + bb[c];
    }
    __syncthreads();

    // phase B: search + gather + combine, store into swizzled [co][px^]
    {
        int px = tid >> 2, j = tid & 3;     // j covers co [j*32, j*32+32)
        float t = sT[px];
        int lo = 0;
        if (j == 0) {
            float key = -t;
            int hi = 1024;
            while (lo < hi) { int mid = (lo + hi) >> 1; if (sPs[mid] > key) hi = mid; else lo = mid + 1; }
        }
        lo = __shfl_sync(0xffffffffu, lo, (tid & 31) & ~3);
        const float4* tp = (const float4*)&g_T12[b][lo][j * 32];
        float* rbase = sRes + (j * 32) * RS + (px ^ (j << 3));
        #pragma unroll
        for (int r = 0; r < 16; r++) {
            float4 f = tp[r];                        // (T1,T2) for co pair
            rbase[(2 * r) * RS]     = fmaf(t, f.x, f.y);
            rbase[(2 * r + 1) * RS] = fmaf(t, f.z, f.w);
        }
    }
    __syncthreads();

    // phase C: BN + residual, coalesced rows
    {
        int co = tid >> 2, q = tid & 3;
        int X  = (co >> 5) << 3;
        float al = sA[co], be = sB[co];
        int xbase = (b * 128 + co) * 4096 + n0;
        #pragma unroll
        for (int r = 0; r < 8; r++) {
            int pos4 = r * 16 + q * 4;
            float4 v = *(float4*)&sRes[co * RS + pos4];
            int px4 = pos4 ^ X;
            float4 xr = *(const float4*)&x[xbase + px4];
            float4 o;
            o.x = fmaf(v.x, al, be) + xr.x;
            o.y = fmaf(v.y, al, be) + xr.y;
            o.z = fmaf(v.z, al, be) + xr.z;
            o.w = fmaf(v.w, al, be) + xr.w;
            *(float4*)&out[xbase + px4] = o;
        }
    }
}

// ---------------------------------------------------------------------------
extern "C" void kernel_launch(void* const* d_in, const int* in_sizes, int n_in,
                              void* d_out, int out_size) {
    const float* x  = (const float*)d_in[0];
    const float* w1 = (const float*)d_in[1];
    const float* b1 = (const float*)d_in[2];
    const float* w3 = (const float*)d_in[3];
    const float* b3 = (const float*)d_in[4];
    const float* w4 = (const float*)d_in[5];
    const float* b4 = (const float*)d_in[6];
    const float* w5 = (const float*)d_in[7];
    const float* w2 = (const float*)d_in[8];
    const float* b2 = (const float*)d_in[9];
    const float* bg = (const float*)d_in[10];
    const float* bb = (const float*)d_in[11];
    const float* bm = (const float*)d_in[12];
    const float* bv = (const float*)d_in[13];
    float* out = (float*)d_out;

    const int k1_smem = (128 * SWS + 64 * SXS) * 4 + (128 + 64 + 132 + 128) * 4;
    const int k3_smem = (1024 + 128 + 128 + 128 + 128 * RS) * 4;
    cudaFuncSetAttribute(k1_conv, cudaFuncAttributeMaxDynamicSharedMemorySize, k1_smem);
    cudaFuncSetAttribute(k3_out,  cudaFuncAttributeMaxDynamicSharedMemorySize, k3_smem);

    k1_conv<<<dim3(32, 8), 256, k1_smem>>>(x, w1, b1, w3, b3, w4, b4, w5);
    k2_sort<<<8, 1024>>>(w2);
    k2z_proj<<<dim3(32, 8), 256>>>();
    k2_scan<<<dim3(32, 8), 256>>>();
    k3_out<<<dim3(32, 8), 512, k3_smem>>>(x, b2, bg, bb, bm, bv, out);
}

// round 12
// speedup vs baseline: 1.1601x; 1.1601x over previous
#include <cuda_runtime.h>
#include <cuda_bf16.h>

// B=8, C=128, IC=64, H=W=64, N=4096, M=1024 (pooled 32x32)

__device__ float g_p[8][1024];
__device__ float g_t[8][4096];
__device__ float g_xg[8][1024][64];
__device__ float g_psort[8][1024];
__device__ int   g_perm[8][1024];
__device__ float2 g_S12[8][1025][64];     // interleaved (S1,S2)
__device__ unsigned g_w2b[4096];          // w2 packed bf16x2 [co][ii]

// ---- helpers --------------------------------------------------------------
__device__ __forceinline__ unsigned pbf2(float lo, float hi) {
    unsigned r; asm("cvt.rn.bf16x2.f32 %0, %1, %2;" : "=r"(r) : "f"(hi), "f"(lo));
    return r;
}
__device__ __forceinline__ void mma16816(float* d, unsigned a0, unsigned a1,
                                         unsigned a2, unsigned a3,
                                         unsigned b0, unsigned b1) {
    asm("mma.sync.aligned.m16n8k16.row.col.f32.bf16.bf16.f32 "
        "{%0,%1,%2,%3}, {%4,%5,%6,%7}, {%8,%9}, {%0,%1,%2,%3};"
        : "+f"(d[0]), "+f"(d[1]), "+f"(d[2]), "+f"(d[3])
        : "r"(a0), "r"(a1), "r"(a2), "r"(a3), "r"(b0), "r"(b1));
}

// ---------------------------------------------------------------------------
// K1: fused conv1+conv4 via bf16 mma.sync, in-register maxpool,
//     + folded conv3 scalar t (wtp folded per block).  (R9 verbatim)
// ---------------------------------------------------------------------------
#define SWS 68
#define SXS 136
__global__ void __launch_bounds__(256, 2)
k1_conv(const float* __restrict__ x,
        const float* __restrict__ w1, const float* __restrict__ b1,
        const float* __restrict__ w3, const float* __restrict__ b3,
        const float* __restrict__ w4, const float* __restrict__ b4,
        const float* __restrict__ w5) {
    extern __shared__ unsigned smu[];
    unsigned* sWb  = smu;                    // 128*68
    unsigned* sXb  = smu + 128 * SWS;        // 64*136
    float* sBias = (float*)(sXb + 64 * SXS); // 128
    float* sWp   = sBias + 128;              // 64
    float* sWtp  = sWp + 64;                 // 132
    float* sPred = sWtp + 132;               // 4*32

    const int tid = threadIdx.x;
    const int pr  = blockIdx.x;
    const int b   = blockIdx.y;

    const float4* w1v = (const float4*)w1;
    const float4* w4v = (const float4*)w4;
    #pragma unroll
    for (int k = 0; k < 16; k++) {
        int v  = tid + k * 256;
        int oc = v >> 5, c4 = v & 31;
        float4 f = (oc < 64) ? w1v[oc * 32 + c4] : w4v[(oc - 64) * 32 + c4];
        *(uint2*)&sWb[oc * SWS + c4 * 2] = make_uint2(pbf2(f.x, f.y), pbf2(f.z, f.w));
    }
    const float4* xv = (const float4*)x;
    #pragma unroll
    for (int it = 0; it < 8; it++) {
        int v   = tid + it * 256;
        int cc  = v >> 5, u = v & 31;
        int r01 = u >> 4, c4 = u & 15;
        float4 fa = xv[((b * 128 + 2 * cc) * 64 + (2 * pr + r01)) * 16 + c4];
        float4 fb = xv[((b * 128 + 2 * cc + 1) * 64 + (2 * pr + r01)) * 16 + c4];
        uint4 q;
        q.x = pbf2(fa.x, fb.x); q.y = pbf2(fa.y, fb.y);
        q.z = pbf2(fa.z, fb.z); q.w = pbf2(fa.w, fb.w);
        *(uint4*)&sXb[cc * SXS + r01 * 64 + c4 * 4] = q;
    }
    if (tid < 128) {
        float acc = 0.f;
        #pragma unroll 16
        for (int i = 0; i < 64; i++) acc = fmaf(w5[i], w3[i * 128 + tid], acc);
        sWtp[tid] = acc;
        sBias[tid] = (tid < 64) ? b1[tid] : b4[tid - 64];
    } else if (tid < 160) {
        int l = tid - 128;
        float s = fmaf(w5[l], b3[l], w5[l + 32] * b3[l + 32]);
        #pragma unroll
        for (int d = 16; d >= 1; d >>= 1)
            s += __shfl_xor_sync(0xffffffffu, s, d);
        if (l == 0) sWtp[128] = s;
    }
    if (tid < 64) sWp[tid] = w5[64 + tid];
    __syncthreads();

    const int w    = tid >> 5;
    const int lane = tid & 31;
    const int g    = lane >> 2;
    const int m4   = lane & 3;
    const int ocb  = w * 16;

    float acc[16][4];
    #pragma unroll
    for (int t = 0; t < 16; t++)
        #pragma unroll
        for (int r = 0; r < 4; r++) acc[t][r] = 0.f;

    #pragma unroll
    for (int s = 0; s < 8; s++) {
        const int cc0 = s * 8;
        unsigned a0 = sWb[(ocb + g)     * SWS + cc0 + m4];
        unsigned a1 = sWb[(ocb + g + 8) * SWS + cc0 + m4];
        unsigned a2 = sWb[(ocb + g)     * SWS + cc0 + 4 + m4];
        unsigned a3 = sWb[(ocb + g + 8) * SWS + cc0 + 4 + m4];
        #pragma unroll
        for (int t = 0; t < 16; t++) {
            unsigned b0 = sXb[(cc0 + m4)     * SXS + t * 8 + g];
            unsigned b1 = sXb[(cc0 + 4 + m4) * SXS + t * 8 + g];
            mma16816(acc[t], a0, a1, a2, a3, b0, b1);
        }
    }

    if (tid < 128) {
        float a = sWtp[128];
        #pragma unroll 8
        for (int cc = 0; cc < 64; cc++) {
            unsigned u = sXb[cc * SXS + tid];
            __nv_bfloat162 h = *reinterpret_cast<__nv_bfloat162*>(&u);
            float2 f = __bfloat1622float2(h);
            a = fmaf(sWtp[2 * cc], f.x, a);
            a = fmaf(sWtp[2 * cc + 1], f.y, a);
        }
        int n = (2 * pr + (tid >> 6)) * 64 + (tid & 63);
        g_t[b][n] = a;
    }

    float pg[8], pg8[8];
    #pragma unroll
    for (int t = 0; t < 8; t++) {
        pg[t]  = fmaxf(fmaxf(acc[t][0], acc[t][1]), fmaxf(acc[t + 8][0], acc[t + 8][1]));
        pg8[t] = fmaxf(fmaxf(acc[t][2], acc[t][3]), fmaxf(acc[t + 8][2], acc[t + 8][3]));
    }

    if (w < 4) {  // xg path: oc 0..63
        int oc0 = ocb + g, oc1 = ocb + g + 8;
        float b0v = sBias[oc0], b1v = sBias[oc1];
        #pragma unroll
        for (int t = 0; t < 8; t++) {
            int mb = pr * 32 + t * 4 + m4;
            g_xg[b][mb][oc0] = pg[t]  + b0v;
            g_xg[b][mb][oc1] = pg8[t] + b1v;
        }
    } else {      // p path
        int oc0 = ocb + g, oc1 = ocb + g + 8;
        float wp0 = sWp[oc0 - 64], wp1 = sWp[oc1 - 64];
        float b0v = sBias[oc0], b1v = sBias[oc1];
        float part[8];
        #pragma unroll
        for (int t = 0; t < 8; t++)
            part[t] = fmaf(wp0, pg[t] + b0v, wp1 * (pg8[t] + b1v));
        #pragma unroll
        for (int d = 4; d < 32; d <<= 1) {
            #pragma unroll
            for (int t = 0; t < 8; t++)
                part[t] += __shfl_xor_sync(0xffffffffu, part[t], d);
        }
        if (lane < 4) {
            #pragma unroll
            for (int t = 0; t < 8; t++)
                sPred[(w - 4) * 32 + t * 4 + lane] = part[t];
        }
    }
    __syncthreads();
    if (tid < 32) {
        float pv = sPred[tid] + sPred[32 + tid] + sPred[64 + tid] + sPred[96 + tid];
        g_p[b][pr * 32 + tid] = pv;
    }
}

// ---------------------------------------------------------------------------
// K2a: bitonic sort (ping-pong smem) + w2 bf16 pack [co][ii]  (R9 verbatim)
// ---------------------------------------------------------------------------
__global__ void __launch_bounds__(1024) k2_sort(const float* __restrict__ w2) {
    __shared__ unsigned long long skA[1024], skB[1024];
    const int b = blockIdx.x, tid = threadIdx.x;

    {
        int u = b * 512 + tid;
        if (tid < 512) {
            float2 f = ((const float2*)w2)[u];
            g_w2b[u] = pbf2(f.x, f.y);
        }
    }

    float v = g_p[b][tid];
    unsigned u = __float_as_uint(v);
    u = (u & 0x80000000u) ? ~u : (u | 0x80000000u);
    unsigned long long key = ((unsigned long long)u << 32) | (unsigned)tid;

    int pb = 0;
    #pragma unroll
    for (int k = 2; k <= 1024; k <<= 1) {
        const bool up = ((tid & k) == 0);
        for (int j = k >> 1; j >= 32; j >>= 1) {
            unsigned long long* buf = pb ? skB : skA;
            buf[tid] = key;
            __syncthreads();
            unsigned long long ok = buf[tid ^ j];
            pb ^= 1;
            bool takeMin = (((tid & j) == 0) == up);
            if ((key > ok) == takeMin) key = ok;
        }
        #pragma unroll
        for (int j = ((k >> 1) < 16 ? (k >> 1) : 16); j >= 1; j >>= 1) {
            unsigned long long ok = __shfl_xor_sync(0xffffffffu, key, j);
            bool takeMin = (((tid & j) == 0) == up);
            if ((key > ok) == takeMin) key = ok;
        }
    }
    int m = (int)(key & 1023u);
    g_perm[b][tid]  = m;
    g_psort[b][tid] = g_p[b][m];
}

// ---------------------------------------------------------------------------
// K2b: suffix scan over xg, 256 threads x 4 j x 4 channels  (R9 verbatim)
// ---------------------------------------------------------------------------
__global__ void __launch_bounds__(256) k2_scan() {
    __shared__ float sm1[4][8], sm2[4][8];
    const int b = blockIdx.y, ig = blockIdx.x;
    const int tid = threadIdx.x, lane = tid & 31, w = tid >> 5;
    const int j0 = 4 * tid;

    if (tid == 0) {
        float2* z = &g_S12[b][1024][ig * 4];
        *(float4*)z       = make_float4(0.f, 0.f, 0.f, 0.f);
        *(float4*)(z + 2) = make_float4(0.f, 0.f, 0.f, 0.f);
    }

    const int4   pm = ((const int4*)g_perm[b])[tid];
    const float4 ps = ((const float4*)g_psort[b])[tid];

    float4 v0 = *(const float4*)&g_xg[b][pm.x][ig * 4];
    float4 v1 = *(const float4*)&g_xg[b][pm.y][ig * 4];
    float4 v2 = *(const float4*)&g_xg[b][pm.z][ig * 4];
    float4 v3 = *(const float4*)&g_xg[b][pm.w][ig * 4];
    float vv[4][4] = {{v0.x, v0.y, v0.z, v0.w}, {v1.x, v1.y, v1.z, v1.w},
                      {v2.x, v2.y, v2.z, v2.w}, {v3.x, v3.y, v3.z, v3.w}};
    float pp[4] = {ps.x, ps.y, ps.z, ps.w};

    float s1[4], s2[4];
    #pragma unroll
    for (int c = 0; c < 4; c++) {
        s1[c] = vv[0][c] + vv[1][c] + vv[2][c] + vv[3][c];
        s2[c] = fmaf(pp[0], vv[0][c], fmaf(pp[1], vv[1][c],
                fmaf(pp[2], vv[2][c], pp[3] * vv[3][c])));
    }

    #pragma unroll
    for (int d = 1; d < 32; d <<= 1) {
        bool take = (lane + d < 32);
        #pragma unroll
        for (int c = 0; c < 4; c++) {
            float t1 = __shfl_down_sync(0xffffffffu, s1[c], d);
            float t2 = __shfl_down_sync(0xffffffffu, s2[c], d);
            if (take) { s1[c] += t1; s2[c] += t2; }
        }
    }
    if (lane == 0) {
        #pragma unroll
        for (int c = 0; c < 4; c++) { sm1[c][w] = s1[c]; sm2[c][w] = s2[c]; }
    }
    __syncthreads();
    #pragma unroll
    for (int c = 0; c < 4; c++) {
        float c1 = 0.f, c2 = 0.f;
        #pragma unroll
        for (int w2i = 0; w2i < 8; w2i++)
            if (w2i > w) { c1 += sm1[c][w2i]; c2 += sm2[c][w2i]; }
        s1[c] += c1; s2[c] += c2;
    }

    float2* base = &g_S12[b][j0][ig * 4];
    #pragma unroll
    for (int k = 0; k < 4; k++) {
        float4 oa = make_float4(s1[0], s2[0], s1[1], s2[1]);
        float4 ob = make_float4(s1[2], s2[2], s1[3], s2[3]);
        float2* dst = base + (long)k * 64;
        *(float4*)dst       = oa;
        *(float4*)(dst + 2) = ob;
        if (k < 3) {
            #pragma unroll
            for (int c = 0; c < 4; c++) {
                s1[c] -= vv[k][c];
                s2[c] = fmaf(-pp[k], vv[k][c], s2[c]);
            }
        }
    }
}

// ---------------------------------------------------------------------------
// K3: R9 structure, but NO w2 smem stage — MMA a-fragments come straight
//     from gmem (L2-resident g_w2b), software-pipelined one k-step ahead.
// grid (32, 8), 512 threads.
// ---------------------------------------------------------------------------
#define YBS2 133
__global__ void __launch_bounds__(512, 2)
k3_out(const float* __restrict__ x,
       const float* __restrict__ b2,
       const float* __restrict__ bg, const float* __restrict__ bb,
       const float* __restrict__ bm, const float* __restrict__ bv,
       float* __restrict__ out) {
    extern __shared__ float sm[];
    unsigned* sYb  = (unsigned*)sm;              // 32*133
    float*    sPs  = (float*)(sYb + 32 * YBS2);  // 1024
    float*    sT   = sPs + 1024;                 // 128
    float*    sA   = sT + 128;                   // 128
    float*    sB   = sA + 128;                   // 128

    const int tid = threadIdx.x;
    const int b   = blockIdx.y;
    const int n00 = blockIdx.x * 128;

    if (tid < 256) {
        ((float4*)sPs)[tid] = ((const float4*)g_psort[b])[tid];
    } else if (tid < 384) {
        sT[tid - 256] = g_t[b][n00 + tid - 256];
    } else {
        int c = tid - 384;
        float inv = rsqrtf(bv[c] + 1e-5f);
        float al  = bg[c] * inv;
        sA[c] = al;
        sB[c] = (b2[c] - bm[c]) * al + bb[c];
    }
    __syncthreads();

    // y build: 4 threads per pixel, inline binary search
    {
        int n = tid >> 2, q = tid & 3;           // n 0..127
        float t = sT[n];
        float key = -t;
        int lo = 0, hi = 1024;
        while (lo < hi) { int mid = (lo + hi) >> 1; if (sPs[mid] > key) hi = mid; else lo = mid + 1; }
        const float4* s4 = (const float4*)&g_S12[b][lo][q * 16];
        #pragma unroll
        for (int r = 0; r < 8; r++) {
            float4 s = s4[r];
            float y0 = fmaf(t, s.x, s.y) * (1.0f / 1024.0f);
            float y1 = fmaf(t, s.z, s.w) * (1.0f / 1024.0f);
            sYb[(q * 8 + r) * YBS2 + n] = pbf2(y0, y1);
        }
    }
    __syncthreads();

    const int w    = tid >> 5;        // 16 warps
    const int lane = tid & 31;
    const int g    = lane >> 2;
    const int m4   = lane & 3;
    const int ocb  = (w & 7) * 16;    // co block
    const int h64  = (w >> 3) * 64;   // pixel half

    float acc[8][4];
    #pragma unroll
    for (int t = 0; t < 8; t++)
        #pragma unroll
        for (int r = 0; r < 4; r++) acc[t][r] = 0.f;

    // a-fragments direct from gmem (L2), pipelined one step ahead
    const unsigned* wb = g_w2b;
    unsigned a0 = wb[(ocb + g)     * 32 + m4];
    unsigned a1 = wb[(ocb + g + 8) * 32 + m4];
    unsigned a2 = wb[(ocb + g)     * 32 + 4 + m4];
    unsigned a3 = wb[(ocb + g + 8) * 32 + 4 + m4];

    #pragma unroll
    for (int s = 0; s < 4; s++) {
        const int ii0 = s * 8;
        unsigned na0 = 0, na1 = 0, na2 = 0, na3 = 0;
        if (s < 3) {
            const int jj = (s + 1) * 8;
            na0 = wb[(ocb + g)     * 32 + jj + m4];
            na1 = wb[(ocb + g + 8) * 32 + jj + m4];
            na2 = wb[(ocb + g)     * 32 + jj + 4 + m4];
            na3 = wb[(ocb + g + 8) * 32 + jj + 4 + m4];
        }
        #pragma unroll
        for (int t = 0; t < 8; t++) {
            unsigned b0 = sYb[(ii0 + m4)     * YBS2 + h64 + t * 8 + g];
            unsigned b1 = sYb[(ii0 + 4 + m4) * YBS2 + h64 + t * 8 + g];
            mma16816(acc[t], a0, a1, a2, a3, b0, b1);
        }
        a0 = na0; a1 = na1; a2 = na2; a3 = na3;
    }

    // epilogue: BN + residual, 32-bit offsets
    const int co0 = ocb + g, co1 = ocb + g + 8;
    const float A0 = sA[co0], B0 = sB[co0];
    const float A1 = sA[co1], B1 = sB[co1];
    const int base0 = ((b * 128 + co0) << 12) + n00 + h64;
    const int base1 = ((b * 128 + co1) << 12) + n00 + h64;
    #pragma unroll
    for (int t = 0; t < 8; t++) {
        int n = t * 8 + 2 * m4;
        float2 x0 = *(const float2*)&x[base0 + n];
        float2 x1 = *(const float2*)&x[base1 + n];
        float2 o0, o1;
        o0.x = fmaf(acc[t][0], A0, B0) + x0.x;
        o0.y = fmaf(acc[t][1], A0, B0) + x0.y;
        o1.x = fmaf(acc[t][2], A1, B1) + x1.x;
        o1.y = fmaf(acc[t][3], A1, B1) + x1.y;
        *(float2*)&out[base0 + n] = o0;
        *(float2*)&out[base1 + n] = o1;
    }
}

// ---------------------------------------------------------------------------
extern "C" void kernel_launch(void* const* d_in, const int* in_sizes, int n_in,
                              void* d_out, int out_size) {
    const float* x  = (const float*)d_in[0];
    const float* w1 = (const float*)d_in[1];
    const float* b1 = (const float*)d_in[2];
    const float* w3 = (const float*)d_in[3];
    const float* b3 = (const float*)d_in[4];
    const float* w4 = (const float*)d_in[5];
    const float* b4 = (const float*)d_in[6];
    const float* w5 = (const float*)d_in[7];
    const float* w2 = (const float*)d_in[8];
    const float* b2 = (const float*)d_in[9];
    const float* bg = (const float*)d_in[10];
    const float* bb = (const float*)d_in[11];
    const float* bm = (const float*)d_in[12];
    const float* bv = (const float*)d_in[13];
    float* out = (float*)d_out;

    const int k1_smem = (128 * SWS + 64 * SXS) * 4 + (128 + 64 + 132 + 128) * 4;
    const int k3_smem = (32 * YBS2) * 4 + (1024 + 128 + 128 + 128) * 4;
    cudaFuncSetAttribute(k1_conv, cudaFuncAttributeMaxDynamicSharedMemorySize, k1_smem);
    cudaFuncSetAttribute(k3_out,  cudaFuncAttributeMaxDynamicSharedMemorySize, k3_smem);

    k1_conv<<<dim3(32, 8), 256, k1_smem>>>(x, w1, b1, w3, b3, w4, b4, w5);
    k2_sort<<<8, 1024>>>(w2);
    k2_scan<<<dim3(16, 8), 256>>>();
    k3_out<<<dim3(32, 8), 512, k3_smem>>>(x, b2, bg, bb, bm, bv, out);
}

// round 13
// speedup vs baseline: 1.2348x; 1.0644x over previous
#include <cuda_runtime.h>
#include <cuda_bf16.h>

// B=8, C=128, IC=64, H=W=64, N=4096, M=1024 (pooled 32x32)

__device__ float g_p[8][1024];
__device__ float g_t[8][4096];
__device__ float g_xg[8][1024][64];
__device__ float g_psort[8][1024];
__device__ int   g_perm[8][1024];
__device__ float2 g_S12[8][1025][64];     // interleaved (S1,S2)
__device__ unsigned g_w2b[4096];          // w2 packed bf16x2 [co][ii]

// ---- helpers --------------------------------------------------------------
__device__ __forceinline__ unsigned pbf2(float lo, float hi) {
    unsigned r; asm("cvt.rn.bf16x2.f32 %0, %1, %2;" : "=r"(r) : "f"(hi), "f"(lo));
    return r;
}
__device__ __forceinline__ void mma16816(float* d, unsigned a0, unsigned a1,
                                         unsigned a2, unsigned a3,
                                         unsigned b0, unsigned b1) {
    asm("mma.sync.aligned.m16n8k16.row.col.f32.bf16.bf16.f32 "
        "{%0,%1,%2,%3}, {%4,%5,%6,%7}, {%8,%9}, {%0,%1,%2,%3};"
        : "+f"(d[0]), "+f"(d[1]), "+f"(d[2]), "+f"(d[3])
        : "r"(a0), "r"(a1), "r"(a2), "r"(a3), "r"(b0), "r"(b1));
}

// ---------------------------------------------------------------------------
// K1: fused conv1+conv4 via bf16 mma.sync, in-register maxpool,
//     + folded conv3 scalar t (wtp folded per block).  (R9 verbatim)
// ---------------------------------------------------------------------------
#define SWS 68
#define SXS 136
__global__ void __launch_bounds__(256, 2)
k1_conv(const float* __restrict__ x,
        const float* __restrict__ w1, const float* __restrict__ b1,
        const float* __restrict__ w3, const float* __restrict__ b3,
        const float* __restrict__ w4, const float* __restrict__ b4,
        const float* __restrict__ w5) {
    extern __shared__ unsigned smu[];
    unsigned* sWb  = smu;                    // 128*68
    unsigned* sXb  = smu + 128 * SWS;        // 64*136
    float* sBias = (float*)(sXb + 64 * SXS); // 128
    float* sWp   = sBias + 128;              // 64
    float* sWtp  = sWp + 64;                 // 132
    float* sPred = sWtp + 132;               // 4*32

    const int tid = threadIdx.x;
    const int pr  = blockIdx.x;
    const int b   = blockIdx.y;

    const float4* w1v = (const float4*)w1;
    const float4* w4v = (const float4*)w4;
    #pragma unroll
    for (int k = 0; k < 16; k++) {
        int v  = tid + k * 256;
        int oc = v >> 5, c4 = v & 31;
        float4 f = (oc < 64) ? w1v[oc * 32 + c4] : w4v[(oc - 64) * 32 + c4];
        *(uint2*)&sWb[oc * SWS + c4 * 2] = make_uint2(pbf2(f.x, f.y), pbf2(f.z, f.w));
    }
    const float4* xv = (const float4*)x;
    #pragma unroll
    for (int it = 0; it < 8; it++) {
        int v   = tid + it * 256;
        int cc  = v >> 5, u = v & 31;
        int r01 = u >> 4, c4 = u & 15;
        float4 fa = xv[((b * 128 + 2 * cc) * 64 + (2 * pr + r01)) * 16 + c4];
        float4 fb = xv[((b * 128 + 2 * cc + 1) * 64 + (2 * pr + r01)) * 16 + c4];
        uint4 q;
        q.x = pbf2(fa.x, fb.x); q.y = pbf2(fa.y, fb.y);
        q.z = pbf2(fa.z, fb.z); q.w = pbf2(fa.w, fb.w);
        *(uint4*)&sXb[cc * SXS + r01 * 64 + c4 * 4] = q;
    }
    if (tid < 128) {
        float acc = 0.f;
        #pragma unroll 16
        for (int i = 0; i < 64; i++) acc = fmaf(w5[i], w3[i * 128 + tid], acc);
        sWtp[tid] = acc;
        sBias[tid] = (tid < 64) ? b1[tid] : b4[tid - 64];
    } else if (tid < 160) {
        int l = tid - 128;
        float s = fmaf(w5[l], b3[l], w5[l + 32] * b3[l + 32]);
        #pragma unroll
        for (int d = 16; d >= 1; d >>= 1)
            s += __shfl_xor_sync(0xffffffffu, s, d);
        if (l == 0) sWtp[128] = s;
    }
    if (tid < 64) sWp[tid] = w5[64 + tid];
    __syncthreads();

    const int w    = tid >> 5;
    const int lane = tid & 31;
    const int g    = lane >> 2;
    const int m4   = lane & 3;
    const int ocb  = w * 16;

    float acc[16][4];
    #pragma unroll
    for (int t = 0; t < 16; t++)
        #pragma unroll
        for (int r = 0; r < 4; r++) acc[t][r] = 0.f;

    #pragma unroll
    for (int s = 0; s < 8; s++) {
        const int cc0 = s * 8;
        unsigned a0 = sWb[(ocb + g)     * SWS + cc0 + m4];
        unsigned a1 = sWb[(ocb + g + 8) * SWS + cc0 + m4];
        unsigned a2 = sWb[(ocb + g)     * SWS + cc0 + 4 + m4];
        unsigned a3 = sWb[(ocb + g + 8) * SWS + cc0 + 4 + m4];
        #pragma unroll
        for (int t = 0; t < 16; t++) {
            unsigned b0 = sXb[(cc0 + m4)     * SXS + t * 8 + g];
            unsigned b1 = sXb[(cc0 + 4 + m4) * SXS + t * 8 + g];
            mma16816(acc[t], a0, a1, a2, a3, b0, b1);
        }
    }

    if (tid < 128) {
        float a = sWtp[128];
        #pragma unroll 8
        for (int cc = 0; cc < 64; cc++) {
            unsigned u = sXb[cc * SXS + tid];
            __nv_bfloat162 h = *reinterpret_cast<__nv_bfloat162*>(&u);
            float2 f = __bfloat1622float2(h);
            a = fmaf(sWtp[2 * cc], f.x, a);
            a = fmaf(sWtp[2 * cc + 1], f.y, a);
        }
        int n = (2 * pr + (tid >> 6)) * 64 + (tid & 63);
        g_t[b][n] = a;
    }

    float pg[8], pg8[8];
    #pragma unroll
    for (int t = 0; t < 8; t++) {
        pg[t]  = fmaxf(fmaxf(acc[t][0], acc[t][1]), fmaxf(acc[t + 8][0], acc[t + 8][1]));
        pg8[t] = fmaxf(fmaxf(acc[t][2], acc[t][3]), fmaxf(acc[t + 8][2], acc[t + 8][3]));
    }

    if (w < 4) {  // xg path: oc 0..63
        int oc0 = ocb + g, oc1 = ocb + g + 8;
        float b0v = sBias[oc0], b1v = sBias[oc1];
        #pragma unroll
        for (int t = 0; t < 8; t++) {
            int mb = pr * 32 + t * 4 + m4;
            g_xg[b][mb][oc0] = pg[t]  + b0v;
            g_xg[b][mb][oc1] = pg8[t] + b1v;
        }
    } else {      // p path
        int oc0 = ocb + g, oc1 = ocb + g + 8;
        float wp0 = sWp[oc0 - 64], wp1 = sWp[oc1 - 64];
        float b0v = sBias[oc0], b1v = sBias[oc1];
        float part[8];
        #pragma unroll
        for (int t = 0; t < 8; t++)
            part[t] = fmaf(wp0, pg[t] + b0v, wp1 * (pg8[t] + b1v));
        #pragma unroll
        for (int d = 4; d < 32; d <<= 1) {
            #pragma unroll
            for (int t = 0; t < 8; t++)
                part[t] += __shfl_xor_sync(0xffffffffu, part[t], d);
        }
        if (lane < 4) {
            #pragma unroll
            for (int t = 0; t < 8; t++)
                sPred[(w - 4) * 32 + t * 4 + lane] = part[t];
        }
    }
    __syncthreads();
    if (tid < 32) {
        float pv = sPred[tid] + sPred[32 + tid] + sPred[64 + tid] + sPred[96 + tid];
        g_p[b][pr * 32 + tid] = pv;
    }
}

// ---------------------------------------------------------------------------
// K2a: bitonic sort (ping-pong smem) + w2 bf16 pack [co][ii]  (R9 verbatim)
// ---------------------------------------------------------------------------
__global__ void __launch_bounds__(1024) k2_sort(const float* __restrict__ w2) {
    __shared__ unsigned long long skA[1024], skB[1024];
    const int b = blockIdx.x, tid = threadIdx.x;

    {
        int u = b * 512 + tid;
        if (tid < 512) {
            float2 f = ((const float2*)w2)[u];
            g_w2b[u] = pbf2(f.x, f.y);
        }
    }

    float v = g_p[b][tid];
    unsigned u = __float_as_uint(v);
    u = (u & 0x80000000u) ? ~u : (u | 0x80000000u);
    unsigned long long key = ((unsigned long long)u << 32) | (unsigned)tid;

    int pb = 0;
    #pragma unroll
    for (int k = 2; k <= 1024; k <<= 1) {
        const bool up = ((tid & k) == 0);
        for (int j = k >> 1; j >= 32; j >>= 1) {
            unsigned long long* buf = pb ? skB : skA;
            buf[tid] = key;
            __syncthreads();
            unsigned long long ok = buf[tid ^ j];
            pb ^= 1;
            bool takeMin = (((tid & j) == 0) == up);
            if ((key > ok) == takeMin) key = ok;
        }
        #pragma unroll
        for (int j = ((k >> 1) < 16 ? (k >> 1) : 16); j >= 1; j >>= 1) {
            unsigned long long ok = __shfl_xor_sync(0xffffffffu, key, j);
            bool takeMin = (((tid & j) == 0) == up);
            if ((key > ok) == takeMin) key = ok;
        }
    }
    int m = (int)(key & 1023u);
    g_perm[b][tid]  = m;
    g_psort[b][tid] = g_p[b][m];
}

// ---------------------------------------------------------------------------
// K2b: suffix scan over xg, 256 threads x 4 j x 4 channels  (R9 verbatim)
// ---------------------------------------------------------------------------
__global__ void __launch_bounds__(256) k2_scan() {
    __shared__ float sm1[4][8], sm2[4][8];
    const int b = blockIdx.y, ig = blockIdx.x;
    const int tid = threadIdx.x, lane = tid & 31, w = tid >> 5;
    const int j0 = 4 * tid;

    if (tid == 0) {
        float2* z = &g_S12[b][1024][ig * 4];
        *(float4*)z       = make_float4(0.f, 0.f, 0.f, 0.f);
        *(float4*)(z + 2) = make_float4(0.f, 0.f, 0.f, 0.f);
    }

    const int4   pm = ((const int4*)g_perm[b])[tid];
    const float4 ps = ((const float4*)g_psort[b])[tid];

    float4 v0 = *(const float4*)&g_xg[b][pm.x][ig * 4];
    float4 v1 = *(const float4*)&g_xg[b][pm.y][ig * 4];
    float4 v2 = *(const float4*)&g_xg[b][pm.z][ig * 4];
    float4 v3 = *(const float4*)&g_xg[b][pm.w][ig * 4];
    float vv[4][4] = {{v0.x, v0.y, v0.z, v0.w}, {v1.x, v1.y, v1.z, v1.w},
                      {v2.x, v2.y, v2.z, v2.w}, {v3.x, v3.y, v3.z, v3.w}};
    float pp[4] = {ps.x, ps.y, ps.z, ps.w};

    float s1[4], s2[4];
    #pragma unroll
    for (int c = 0; c < 4; c++) {
        s1[c] = vv[0][c] + vv[1][c] + vv[2][c] + vv[3][c];
        s2[c] = fmaf(pp[0], vv[0][c], fmaf(pp[1], vv[1][c],
                fmaf(pp[2], vv[2][c], pp[3] * vv[3][c])));
    }

    #pragma unroll
    for (int d = 1; d < 32; d <<= 1) {
        bool take = (lane + d < 32);
        #pragma unroll
        for (int c = 0; c < 4; c++) {
            float t1 = __shfl_down_sync(0xffffffffu, s1[c], d);
            float t2 = __shfl_down_sync(0xffffffffu, s2[c], d);
            if (take) { s1[c] += t1; s2[c] += t2; }
        }
    }
    if (lane == 0) {
        #pragma unroll
        for (int c = 0; c < 4; c++) { sm1[c][w] = s1[c]; sm2[c][w] = s2[c]; }
    }
    __syncthreads();
    #pragma unroll
    for (int c = 0; c < 4; c++) {
        float c1 = 0.f, c2 = 0.f;
        #pragma unroll
        for (int w2i = 0; w2i < 8; w2i++)
            if (w2i > w) { c1 += sm1[c][w2i]; c2 += sm2[c][w2i]; }
        s1[c] += c1; s2[c] += c2;
    }

    float2* base = &g_S12[b][j0][ig * 4];
    #pragma unroll
    for (int k = 0; k < 4; k++) {
        float4 oa = make_float4(s1[0], s2[0], s1[1], s2[1]);
        float4 ob = make_float4(s1[2], s2[2], s1[3], s2[3]);
        float2* dst = base + (long)k * 64;
        *(float4*)dst       = oa;
        *(float4*)(dst + 2) = ob;
        if (k < 3) {
            #pragma unroll
            for (int c = 0; c < 4; c++) {
                s1[c] -= vv[k][c];
                s2[c] = fmaf(-pp[k], vv[k][c], s2[c]);
            }
        }
    }
}

// ---------------------------------------------------------------------------
// K3: R9 structure, single-wave grid (16,8)=128 blocks, 512 threads,
//     256 pixels per block processed as two 128-px halves reusing the
//     staged w2/psort/BN.  (R9 k3 otherwise verbatim)
// ---------------------------------------------------------------------------
#define W2S 36
#define YBS2 133
__global__ void __launch_bounds__(512, 2)
k3_out(const float* __restrict__ x,
       const float* __restrict__ b2,
       const float* __restrict__ bg, const float* __restrict__ bb,
       const float* __restrict__ bm, const float* __restrict__ bv,
       float* __restrict__ out) {
    extern __shared__ float sm[];
    unsigned* sW2b = (unsigned*)sm;              // 128*36 = 4608
    unsigned* sYb  = sW2b + 128 * W2S;           // 32*133 = 4256
    float*    sPs  = (float*)(sYb + 32 * YBS2);  // 1024
    float*    sT   = sPs + 1024;                 // 256
    float*    sA   = sT + 256;                   // 128
    float*    sB   = sA + 128;                   // 128

    const int tid = threadIdx.x;
    const int b   = blockIdx.y;
    const int n00 = blockIdx.x * 256;

    // stage packed w2 (bf16, 16KB): 2 uint4 per thread
    const uint4* w2b4 = (const uint4*)g_w2b;     // 1024 uint4
    #pragma unroll
    for (int k = 0; k < 2; k++) {
        int v = tid + k * 512;
        int co = v >> 3, q4 = v & 7;
        *(uint4*)&sW2b[co * W2S + q4 * 4] = w2b4[v];
    }
    if (tid < 256) {
        ((float4*)sPs)[tid] = ((const float4*)g_psort[b])[tid];
    } else {
        sT[tid - 256] = g_t[b][n00 + tid - 256];
    }
    if (tid >= 128 && tid < 256) {
        int c = tid - 128;
        float inv = rsqrtf(bv[c] + 1e-5f);
        float al  = bg[c] * inv;
        sA[c] = al;
        sB[c] = (b2[c] - bm[c]) * al + bb[c];
    }
    __syncthreads();

    const int w    = tid >> 5;        // 16 warps
    const int lane = tid & 31;
    const int g    = lane >> 2;
    const int m4   = lane & 3;
    const int ocb  = (w & 7) * 16;    // co block
    const int h64  = (w >> 3) * 64;   // pixel half within the 128-px tile

    #pragma unroll 1
    for (int h = 0; h < 2; h++) {
        const int nb = h * 128;

        // y build: 4 threads per pixel, inline binary search
        {
            int n = tid >> 2, q = tid & 3;       // n 0..127
            float t = sT[nb + n];
            float key = -t;
            int lo = 0, hi = 1024;
            while (lo < hi) { int mid = (lo + hi) >> 1; if (sPs[mid] > key) hi = mid; else lo = mid + 1; }
            const float4* s4 = (const float4*)&g_S12[b][lo][q * 16];
            #pragma unroll
            for (int r = 0; r < 8; r++) {
                float4 s = s4[r];
                float y0 = fmaf(t, s.x, s.y) * (1.0f / 1024.0f);
                float y1 = fmaf(t, s.z, s.w) * (1.0f / 1024.0f);
                sYb[(q * 8 + r) * YBS2 + n] = pbf2(y0, y1);
            }
        }
        __syncthreads();

        float acc[8][4];
        #pragma unroll
        for (int t = 0; t < 8; t++)
            #pragma unroll
            for (int r = 0; r < 4; r++) acc[t][r] = 0.f;

        #pragma unroll
        for (int s = 0; s < 4; s++) {
            const int ii0 = s * 8;
            unsigned a0 = sW2b[(ocb + g)     * W2S + ii0 + m4];
            unsigned a1 = sW2b[(ocb + g + 8) * W2S + ii0 + m4];
            unsigned a2 = sW2b[(ocb + g)     * W2S + ii0 + 4 + m4];
            unsigned a3 = sW2b[(ocb + g + 8) * W2S + ii0 + 4 + m4];
            #pragma unroll
            for (int t = 0; t < 8; t++) {
                unsigned b0 = sYb[(ii0 + m4)     * YBS2 + h64 + t * 8 + g];
                unsigned b1 = sYb[(ii0 + 4 + m4) * YBS2 + h64 + t * 8 + g];
                mma16816(acc[t], a0, a1, a2, a3, b0, b1);
            }
        }

        // epilogue: BN + residual, 32-bit offsets
        const int co0 = ocb + g, co1 = ocb + g + 8;
        const float A0 = sA[co0], B0 = sB[co0];
        const float A1 = sA[co1], B1 = sB[co1];
        const int base0 = ((b * 128 + co0) << 12) + n00 + nb + h64;
        const int base1 = ((b * 128 + co1) << 12) + n00 + nb + h64;
        #pragma unroll
        for (int t = 0; t < 8; t++) {
            int n = t * 8 + 2 * m4;
            float2 x0 = *(const float2*)&x[base0 + n];
            float2 x1 = *(const float2*)&x[base1 + n];
            float2 o0, o1;
            o0.x = fmaf(acc[t][0], A0, B0) + x0.x;
            o0.y = fmaf(acc[t][1], A0, B0) + x0.y;
            o1.x = fmaf(acc[t][2], A1, B1) + x1.x;
            o1.y = fmaf(acc[t][3], A1, B1) + x1.y;
            *(float2*)&out[base0 + n] = o0;
            *(float2*)&out[base1 + n] = o1;
        }
        __syncthreads();   // protect sYb before next half overwrites it
    }
}

// ---------------------------------------------------------------------------
extern "C" void kernel_launch(void* const* d_in, const int* in_sizes, int n_in,
                              void* d_out, int out_size) {
    const float* x  = (const float*)d_in[0];
    const float* w1 = (const float*)d_in[1];
    const float* b1 = (const float*)d_in[2];
    const float* w3 = (const float*)d_in[3];
    const float* b3 = (const float*)d_in[4];
    const float* w4 = (const float*)d_in[5];
    const float* b4 = (const float*)d_in[6];
    const float* w5 = (const float*)d_in[7];
    const float* w2 = (const float*)d_in[8];
    const float* b2 = (const float*)d_in[9];
    const float* bg = (const float*)d_in[10];
    const float* bb = (const float*)d_in[11];
    const float* bm = (const float*)d_in[12];
    const float* bv = (const float*)d_in[13];
    float* out = (float*)d_out;

    const int k1_smem = (128 * SWS + 64 * SXS) * 4 + (128 + 64 + 132 + 128) * 4;
    const int k3_smem = (128 * W2S + 32 * YBS2) * 4 + (1024 + 256 + 128 + 128) * 4;
    cudaFuncSetAttribute(k1_conv, cudaFuncAttributeMaxDynamicSharedMemorySize, k1_smem);
    cudaFuncSetAttribute(k3_out,  cudaFuncAttributeMaxDynamicSharedMemorySize, k3_smem);

    k1_conv<<<dim3(32, 8), 256, k1_smem>>>(x, w1, b1, w3, b3, w4, b4, w5);
    k2_sort<<<8, 1024>>>(w2);
    k2_scan<<<dim3(16, 8), 256>>>();
    k3_out<<<dim3(16, 8), 512, k3_smem>>>(x, b2, bg, bb, bm, bv, out);
}